// round 9
// baseline (speedup 1.0000x reference)
#include <cuda_runtime.h>
#include <math.h>

#define BB 64
#define TT 512
#define II 256
#define HH 512
#define CC 128

// Scratch (static device allocations are allowed; cudaMalloc is not)
__device__ float g_gates[(size_t)TT * BB * 4 * HH];   // [t][b][4H]  256 MB
__device__ float g_hs[(size_t)TT * BB * HH];          // [t][b][H]    64 MB
__device__ float g_h[2][BB * HH];                     // ping-pong h state

// Flag-array barriers: 4 batch groups x 32 CTA slots, each slot on its own
// 128-byte line (no atomic serialization, no shared-line contention).
__device__ unsigned int g_flags[4][32][32];
// One-shot full-grid barrier (replay-safe, generation counting) for init.
__device__ unsigned int g_bar_count;
__device__ unsigned int g_bar_gen;

__device__ __forceinline__ float sigmoidf_(float x) {
    return 1.0f / (1.0f + expf(-x));
}

// Packed dual-FMA: acc(lo,hi) += a(lo,hi) * b(lo,hi)   (ptxas never auto-fuses)
__device__ __forceinline__ void ffma2(unsigned long long& acc,
                                      unsigned long long a,
                                      unsigned long long b) {
    asm("fma.rn.f32x2 %0, %1, %2, %0;" : "+l"(acc) : "l"(a), "l"(b));
}

__device__ __forceinline__ unsigned long long pack2(float x) {
    unsigned long long r;
    asm("mov.b64 %0, {%1, %1};" : "=l"(r) : "f"(x));
    return r;
}

__device__ __forceinline__ float pairsum(unsigned long long v) {
    float2 f = *(float2*)&v;
    return f.x + f.y;
}

// Volatile L2 load/store for barrier flags (compiler must not hoist/CSE).
__device__ __forceinline__ unsigned int ldcg_u32v(const unsigned int* p) {
    unsigned int v;
    asm volatile("ld.global.cg.u32 %0, [%1];" : "=r"(v) : "l"(p));
    return v;
}
__device__ __forceinline__ unsigned int ldacq_u32(const unsigned int* p) {
    unsigned int v;
    asm volatile("ld.global.acquire.gpu.u32 %0, [%1];" : "=r"(v) : "l"(p));
    return v;
}
__device__ __forceinline__ void stcg_u32v(unsigned int* p, unsigned int v) {
    asm volatile("st.global.cg.u32 [%0], %1;" :: "l"(p), "r"(v) : "memory");
}

// ---------------------------------------------------------------------------
// Phase 1: G[t][b][n] = x[b][t][:] . W_ih[n][:] + b_ih[n] + b_hh[n]
// (unchanged — 790 us, 57% fma)
// ---------------------------------------------------------------------------
__global__ void __launch_bounds__(256) gates_gemm(
    const float* __restrict__ x,
    const float* __restrict__ W_ih,
    const float* __restrict__ b_ih,
    const float* __restrict__ b_hh)
{
    __shared__ float As[8][128];
    __shared__ float Bs[8][128];

    const int n0 = blockIdx.x * 128;
    const int m0 = blockIdx.y * 128;
    const int tid = threadIdx.x;
    const int tx = tid & 15;
    const int ty = tid >> 4;

    unsigned long long acc2[8][4];
#pragma unroll
    for (int i = 0; i < 8; i++)
#pragma unroll
        for (int j = 0; j < 4; j++) acc2[i][j] = 0ull;

    const int lr = tid >> 1;
    const int lk = (tid & 1) * 4;

    for (int k0 = 0; k0 < II; k0 += 8) {
        {
            float4 v = *(const float4*)(x + (size_t)(m0 + lr) * II + k0 + lk);
            As[lk + 0][lr] = v.x; As[lk + 1][lr] = v.y;
            As[lk + 2][lr] = v.z; As[lk + 3][lr] = v.w;
        }
        {
            float4 v = *(const float4*)(W_ih + (size_t)(n0 + lr) * II + k0 + lk);
            Bs[lk + 0][lr] = v.x; Bs[lk + 1][lr] = v.y;
            Bs[lk + 2][lr] = v.z; Bs[lk + 3][lr] = v.w;
        }
        __syncthreads();
#pragma unroll
        for (int k = 0; k < 8; k++) {
            float a[8];
            float4 a0 = *(const float4*)&As[k][ty * 4];
            float4 a1 = *(const float4*)&As[k][64 + ty * 4];
            ulonglong2 bp0 = *(const ulonglong2*)&Bs[k][tx * 4];
            ulonglong2 bp1 = *(const ulonglong2*)&Bs[k][64 + tx * 4];
            a[0]=a0.x; a[1]=a0.y; a[2]=a0.z; a[3]=a0.w;
            a[4]=a1.x; a[5]=a1.y; a[6]=a1.z; a[7]=a1.w;
#pragma unroll
            for (int i = 0; i < 8; i++) {
                unsigned long long a2 = pack2(a[i]);
                ffma2(acc2[i][0], a2, bp0.x);
                ffma2(acc2[i][1], a2, bp0.y);
                ffma2(acc2[i][2], a2, bp1.x);
                ffma2(acc2[i][3], a2, bp1.y);
            }
        }
        __syncthreads();
    }

#pragma unroll
    for (int i = 0; i < 8; i++) {
        int m = m0 + (i >> 2) * 64 + ty * 4 + (i & 3);
        int bb = m >> 9;
        int tt = m & 511;
        size_t row = ((size_t)tt * BB + bb) * (4 * HH);
#pragma unroll
        for (int j2 = 0; j2 < 4; j2++) {
            float2 f = *(float2*)&acc2[i][j2];
            int jlo = j2 * 2;
            int n0c = n0 + (jlo >> 2) * 64 + tx * 4 + (jlo & 3);
            g_gates[row + n0c]     = f.x + b_ih[n0c]     + b_hh[n0c];
            g_gates[row + n0c + 1] = f.y + b_ih[n0c + 1] + b_hh[n0c + 1];
        }
    }
}

// ---------------------------------------------------------------------------
// Phase 2: persistent recurrence, 2-D sharded (R5/R8 shape), with
// slice-wise pipelined staging:
//  - h columns k in [s*16,(s+1)*16) are produced by CTA slot s of the group.
//  - each warp owns 4 slices: poll flag[s] (acquire), then copy that 1KB
//    slice immediately -> staging overlaps with straggler CTAs, and the
//    critical path is last-flag + 1KB copy instead of all-flags + 32KB.
//  - 2 bars/step instead of 3; gate inputs prefetched one step ahead.
// ---------------------------------------------------------------------------
#define W_PITCH 129                 // float4 units per (jl,gate) row (pad vs 128)
#define H_PITCH 516                 // floats per staged h row (pad vs 512)
#define WSM_F4  (16 * 4 * W_PITCH)              // float4 count for weights
#define SMEM_RECUR ((WSM_F4 * 16) + (16 * H_PITCH * 4))   // bytes

__global__ void __launch_bounds__(256) lstm_recur(const float* __restrict__ W_hh)
{
    extern __shared__ float smem[];
    float4* Ws4 = (float4*)smem;                      // [ (jl*4+gate)*W_PITCH + k4 ]
    float*  hsm = smem + WSM_F4 * 4;                  // [ bl*H_PITCH + k ]

    const int tid  = threadIdx.x;
    const int lane = tid & 31;
    const int wid  = tid >> 5;         // 0..7
    const int bl   = tid & 15;         // batch-lane 0..15
    const int jl   = tid >> 4;         // unit-lane  0..15
    const int bg   = blockIdx.x & 3;
    const int jg   = blockIdx.x >> 2;  // 0..31 = slot in this bg's barrier
    const int b    = bg * 16 + bl;
    const int j    = jg * 16 + jl;
    const int j0   = jg * 16;

    // Load this CTA's W_hh slice: rows (gate*H + j0+u), u=0..15. 8192 float4s.
    for (int idx = tid; idx < 16 * 4 * 128; idx += 256) {
        int u   = idx >> 9;            // 0..15
        int rem = idx & 511;
        int g   = rem >> 7;            // 0..3
        int k4  = rem & 127;
        Ws4[(u * 4 + g) * W_PITCH + k4] =
            *(const float4*)(W_hh + ((size_t)(g * HH + j0 + u)) * HH + k4 * 4);
    }

    // init read-buffer h to 0 and reset our flag slot (fresh every replay)
    __stcg(&g_h[0][b * HH + j], 0.0f);
    if (tid == 0) stcg_u32v(&g_flags[bg][jg][0], 0u);
    float c = 0.0f;

    // One-shot full-grid barrier: orders h-zero + flag resets across ALL CTAs
    // before any flag-wait can observe them. (Atomic cost paid once only.)
    __threadfence();
    __syncthreads();
    if (tid == 0) {
        unsigned int my = *((volatile unsigned int*)&g_bar_gen);
        unsigned int arrived = atomicAdd(&g_bar_count, 1u);
        if (arrived == (unsigned)gridDim.x - 1) {
            atomicExch(&g_bar_count, 0u);
            __threadfence();
            atomicAdd(&g_bar_gen, 1u);
        } else {
            while (*((volatile unsigned int*)&g_bar_gen) == my) { __nanosleep(32); }
        }
        __threadfence();
    }
    __syncthreads();

    const ulonglong2* Wi = (const ulonglong2*)(Ws4 + (jl * 4 + 0) * W_PITCH);
    const ulonglong2* Wf = (const ulonglong2*)(Ws4 + (jl * 4 + 1) * W_PITCH);
    const ulonglong2* Wg = (const ulonglong2*)(Ws4 + (jl * 4 + 2) * W_PITCH);
    const ulonglong2* Wo = (const ulonglong2*)(Ws4 + (jl * 4 + 3) * W_PITCH);
    const ulonglong2* Hr = (const ulonglong2*)(hsm + bl * H_PITCH);

    // Initial stage of h[0] (zeros; no flags needed — grid barrier ordered it).
    {
        const float* hsrc = &g_h[0][(bg * 16) * HH];
#pragma unroll
        for (int i = 0; i < 8; i++) {
            int idx  = i * 256 + tid;          // 0..2047 float4s
            int brow = idx >> 7;
            int k4   = idx & 127;
            float4 v = __ldcg((const float4*)(hsrc + (size_t)brow * HH) + k4);
            *(float4*)(hsm + brow * H_PITCH + k4 * 4) = v;
        }
    }
    // Preload gate inputs for t=0.
    const float* xgp = &g_gates[(size_t)b * (4 * HH) + j];
    float xi  = __ldcg(xgp);
    float xf  = __ldcg(xgp + HH);
    float xgg = __ldcg(xgp + 2 * HH);
    float xo  = __ldcg(xgp + 3 * HH);
    __syncthreads();

    for (int t = 0; t < TT; t++) {
        unsigned long long ai = 0ull, af = 0ull, ag = 0ull, ao = 0ull;
#pragma unroll 8
        for (int k4 = 0; k4 < 128; k4++) {
            ulonglong2 h2 = Hr[k4];
            ulonglong2 wi = Wi[k4];
            ulonglong2 wf = Wf[k4];
            ulonglong2 wg = Wg[k4];
            ulonglong2 wo = Wo[k4];
            ffma2(ai, h2.x, wi.x); ffma2(ai, h2.y, wi.y);
            ffma2(af, h2.x, wf.x); ffma2(af, h2.y, wf.y);
            ffma2(ag, h2.x, wg.x); ffma2(ag, h2.y, wg.y);
            ffma2(ao, h2.x, wo.x); ffma2(ao, h2.y, wo.y);
        }

        float gi = sigmoidf_(xi  + pairsum(ai));
        float gf = sigmoidf_(xf  + pairsum(af));
        float gg = tanhf    (xgg + pairsum(ag));
        float go = sigmoidf_(xo  + pairsum(ao));
        c = gf * c + gi * gg;
        float hv = go * tanhf(c);
        __stcg(&g_h[(t + 1) & 1][b * HH + j], hv);

        if (t == TT - 1) {
            g_hs[((size_t)t * BB + b) * HH + j] = hv;
            break;
        }

        // ---- signal: fence own stores, CTA-sync, set flag ----
        __threadfence();                 // h stcg gpu-visible
        __syncthreads();                 // all 256 threads fenced
        if (tid == 0) stcg_u32v(&g_flags[bg][jg][0], (unsigned int)(t + 1));

        // History store + next-step gate prefetch ride the poll window.
        g_hs[((size_t)t * BB + b) * HH + j] = hv;
        {
            const float* xg = &g_gates[((size_t)(t + 1) * BB + b) * (4 * HH) + j];
            xi  = __ldcg(xg);
            xf  = __ldcg(xg + HH);
            xgg = __ldcg(xg + 2 * HH);
            xo  = __ldcg(xg + 3 * HH);
        }

        // ---- slice-wise pipelined stage of h[t+1] ----
        // Slice s (k in [s*16,(s+1)*16)) is produced by CTA slot s; copy it
        // as soon as that CTA's flag lands. Warp w owns slices w, w+8, ...
        {
            const float* hbuf = &g_h[(t + 1) & 1][(bg * 16) * HH];
            unsigned int tgt = (unsigned int)(t + 1);
            const int q = lane & 3;           // float4 within slice row
            const int r = lane >> 2;          // 0..7
#pragma unroll
            for (int sidx = 0; sidx < 4; sidx++) {
                int sl = wid + sidx * 8;
                if (lane == 0) {
                    while (ldcg_u32v(&g_flags[bg][sl][0]) < tgt) { __nanosleep(20); }
                }
                __syncwarp();
                (void)ldacq_u32(&g_flags[bg][sl][0]);   // acquire for whole warp
#pragma unroll
                for (int half = 0; half < 2; half++) {
                    int row = half * 8 + r;
                    float4 v = __ldcg((const float4*)(hbuf + (size_t)row * HH + sl * 16) + q);
                    *(float4*)(hsm + row * H_PITCH + sl * 16 + q * 4) = v;
                }
            }
        }
        __syncthreads();   // staged h[t+1] visible to all warps
    }
}

// ---------------------------------------------------------------------------
// Phase 3: out[b][t][c] = hs[t][b][:] . W_fc[c][:] + b_fc[c]  (unchanged)
// ---------------------------------------------------------------------------
__global__ void __launch_bounds__(256) fc_gemm(
    const float* __restrict__ W_fc,
    const float* __restrict__ b_fc,
    float* __restrict__ out)
{
    __shared__ float As[8][128];
    __shared__ float Bs[8][128];

    const int m0 = blockIdx.x * 128;
    const int tid = threadIdx.x;
    const int tx = tid & 15;
    const int ty = tid >> 4;

    float acc[8][8];
#pragma unroll
    for (int i = 0; i < 8; i++)
#pragma unroll
        for (int j = 0; j < 8; j++) acc[i][j] = 0.0f;

    const int lr = tid >> 1;
    const int lk = (tid & 1) * 4;

    for (int k0 = 0; k0 < HH; k0 += 8) {
        {
            float4 v = *(const float4*)(g_hs + (size_t)(m0 + lr) * HH + k0 + lk);
            As[lk + 0][lr] = v.x; As[lk + 1][lr] = v.y;
            As[lk + 2][lr] = v.z; As[lk + 3][lr] = v.w;
        }
        {
            float4 v = *(const float4*)(W_fc + (size_t)lr * HH + k0 + lk);
            Bs[lk + 0][lr] = v.x; Bs[lk + 1][lr] = v.y;
            Bs[lk + 2][lr] = v.z; Bs[lk + 3][lr] = v.w;
        }
        __syncthreads();
#pragma unroll
        for (int k = 0; k < 8; k++) {
            float a[8], b[8];
            float4 a0 = *(const float4*)&As[k][ty * 4];
            float4 a1 = *(const float4*)&As[k][64 + ty * 4];
            float4 b0 = *(const float4*)&Bs[k][tx * 4];
            float4 b1 = *(const float4*)&Bs[k][64 + tx * 4];
            a[0]=a0.x; a[1]=a0.y; a[2]=a0.z; a[3]=a0.w;
            a[4]=a1.x; a[5]=a1.y; a[6]=a1.z; a[7]=a1.w;
            b[0]=b0.x; b[1]=b0.y; b[2]=b0.z; b[3]=b0.w;
            b[4]=b1.x; b[5]=b1.y; b[6]=b1.z; b[7]=b1.w;
#pragma unroll
            for (int i = 0; i < 8; i++)
#pragma unroll
                for (int j = 0; j < 8; j++)
                    acc[i][j] = fmaf(a[i], b[j], acc[i][j]);
        }
        __syncthreads();
    }

#pragma unroll
    for (int i = 0; i < 8; i++) {
        int m = m0 + (i >> 2) * 64 + ty * 4 + (i & 3);
        int bb = m & 63;
        int tt = m >> 6;
        size_t orow = ((size_t)bb * TT + tt) * CC;
#pragma unroll
        for (int j = 0; j < 8; j++) {
            int cc = (j >> 2) * 64 + tx * 4 + (j & 3);
            out[orow + cc] = acc[i][j] + b_fc[cc];
        }
    }
}

// ---------------------------------------------------------------------------
extern "C" void kernel_launch(void* const* d_in, const int* in_sizes, int n_in,
                              void* d_out, int out_size)
{
    const float* x    = (const float*)d_in[0];
    const float* W_ih = (const float*)d_in[1];
    const float* W_hh = (const float*)d_in[2];
    const float* b_ih = (const float*)d_in[3];
    const float* b_hh = (const float*)d_in[4];
    const float* W_fc = (const float*)d_in[5];
    const float* b_fc = (const float*)d_in[6];
    float* out = (float*)d_out;

    cudaFuncSetAttribute(lstm_recur,
                         cudaFuncAttributeMaxDynamicSharedMemorySize,
                         SMEM_RECUR);

    dim3 g1(4 * HH / 128, (BB * TT) / 128);   // (16, 256)
    gates_gemm<<<g1, 256>>>(x, W_ih, b_ih, b_hh);

    lstm_recur<<<128, 256, SMEM_RECUR>>>(W_hh);   // 128 CTAs, co-resident

    fc_gemm<<<(BB * TT) / 128, 256>>>(W_fc, b_fc, out);
}

// round 10
// speedup vs baseline: 1.6724x; 1.6724x over previous
#include <cuda_runtime.h>
#include <math.h>

#define BB 64
#define TT 512
#define II 256
#define HH 512
#define CC 128

// Scratch (static device allocations are allowed; cudaMalloc is not)
__device__ float g_gates[(size_t)TT * BB * 4 * HH];   // [t][b][4H]  256 MB
__device__ float g_hs[(size_t)TT * BB * HH];          // [t][b][H]    64 MB
__device__ float g_h[2][BB * HH];                     // ping-pong h state

// Flag-array barriers: 4 batch groups x 32 CTA slots, each slot on its own
// 128-byte line (no atomic serialization, no shared-line contention).
__device__ unsigned int g_flags[4][32][32];
// One-shot full-grid barrier (replay-safe, generation counting) for init.
__device__ unsigned int g_bar_count;
__device__ unsigned int g_bar_gen;

__device__ __forceinline__ float sigmoidf_(float x) {
    return 1.0f / (1.0f + expf(-x));
}

// Packed dual-FMA: acc(lo,hi) += a(lo,hi) * b(lo,hi)   (ptxas never auto-fuses)
__device__ __forceinline__ void ffma2(unsigned long long& acc,
                                      unsigned long long a,
                                      unsigned long long b) {
    asm("fma.rn.f32x2 %0, %1, %2, %0;" : "+l"(acc) : "l"(a), "l"(b));
}

__device__ __forceinline__ unsigned long long pack2(float x) {
    unsigned long long r;
    asm("mov.b64 %0, {%1, %1};" : "=l"(r) : "f"(x));
    return r;
}

__device__ __forceinline__ float pairsum(unsigned long long v) {
    float2 f = *(float2*)&v;
    return f.x + f.y;
}

// Volatile L2 load/store for barrier flags (compiler must not hoist/CSE).
__device__ __forceinline__ unsigned int ldcg_u32v(const unsigned int* p) {
    unsigned int v;
    asm volatile("ld.global.cg.u32 %0, [%1];" : "=r"(v) : "l"(p));
    return v;
}
__device__ __forceinline__ void stcg_u32v(unsigned int* p, unsigned int v) {
    asm volatile("st.global.cg.u32 [%0], %1;" :: "l"(p), "r"(v) : "memory");
}

// ---------------------------------------------------------------------------
// Phase 1: G[t][b][n] = x[b][t][:] . W_ih[n][:] + b_ih[n] + b_hh[n]
// (unchanged)
// ---------------------------------------------------------------------------
__global__ void __launch_bounds__(256) gates_gemm(
    const float* __restrict__ x,
    const float* __restrict__ W_ih,
    const float* __restrict__ b_ih,
    const float* __restrict__ b_hh)
{
    __shared__ float As[8][128];
    __shared__ float Bs[8][128];

    const int n0 = blockIdx.x * 128;
    const int m0 = blockIdx.y * 128;
    const int tid = threadIdx.x;
    const int tx = tid & 15;
    const int ty = tid >> 4;

    unsigned long long acc2[8][4];
#pragma unroll
    for (int i = 0; i < 8; i++)
#pragma unroll
        for (int j = 0; j < 4; j++) acc2[i][j] = 0ull;

    const int lr = tid >> 1;
    const int lk = (tid & 1) * 4;

    for (int k0 = 0; k0 < II; k0 += 8) {
        {
            float4 v = *(const float4*)(x + (size_t)(m0 + lr) * II + k0 + lk);
            As[lk + 0][lr] = v.x; As[lk + 1][lr] = v.y;
            As[lk + 2][lr] = v.z; As[lk + 3][lr] = v.w;
        }
        {
            float4 v = *(const float4*)(W_ih + (size_t)(n0 + lr) * II + k0 + lk);
            Bs[lk + 0][lr] = v.x; Bs[lk + 1][lr] = v.y;
            Bs[lk + 2][lr] = v.z; Bs[lk + 3][lr] = v.w;
        }
        __syncthreads();
#pragma unroll
        for (int k = 0; k < 8; k++) {
            float a[8];
            float4 a0 = *(const float4*)&As[k][ty * 4];
            float4 a1 = *(const float4*)&As[k][64 + ty * 4];
            ulonglong2 bp0 = *(const ulonglong2*)&Bs[k][tx * 4];
            ulonglong2 bp1 = *(const ulonglong2*)&Bs[k][64 + tx * 4];
            a[0]=a0.x; a[1]=a0.y; a[2]=a0.z; a[3]=a0.w;
            a[4]=a1.x; a[5]=a1.y; a[6]=a1.z; a[7]=a1.w;
#pragma unroll
            for (int i = 0; i < 8; i++) {
                unsigned long long a2 = pack2(a[i]);
                ffma2(acc2[i][0], a2, bp0.x);
                ffma2(acc2[i][1], a2, bp0.y);
                ffma2(acc2[i][2], a2, bp1.x);
                ffma2(acc2[i][3], a2, bp1.y);
            }
        }
        __syncthreads();
    }

#pragma unroll
    for (int i = 0; i < 8; i++) {
        int m = m0 + (i >> 2) * 64 + ty * 4 + (i & 3);
        int bb = m >> 9;
        int tt = m & 511;
        size_t row = ((size_t)tt * BB + bb) * (4 * HH);
#pragma unroll
        for (int j2 = 0; j2 < 4; j2++) {
            float2 f = *(float2*)&acc2[i][j2];
            int jlo = j2 * 2;
            int n0c = n0 + (jlo >> 2) * 64 + tx * 4 + (jlo & 3);
            g_gates[row + n0c]     = f.x + b_ih[n0c]     + b_hh[n0c];
            g_gates[row + n0c + 1] = f.y + b_ih[n0c + 1] + b_hh[n0c + 1];
        }
    }
}

// ---------------------------------------------------------------------------
// Phase 2: persistent recurrence, register-resident weights.
// Grid = 128 CTAs (bg 0..3, jg 0..31), 256 threads. Sync protocol = R8.
// Compute: thread (jl=tid>>4, kc=tid&15) holds W[4g][j0+jl][kc*32..+31] in
//   128 regs (loaded ONCE). Per step, per b: 8 swizzled h-LDS.128 + 64 FFMA2,
//   then a float4 partial {i,f,g,o} -> psm. (Zero W smem traffic per step.)
// Reduce: thread (bl=tid&15, jl=tid>>4) sums 16 kc-partials, adds xg, runs
//   activations, updates its resident c, stores h. (c ownership unchanged.)
// h staging uses XOR swizzle: source float4 k4 (kc=k4>>3, q=k4&7) stored at
//   slot kc*8 + (q ^ (kc&7)) so compute's kc-strided reads are phase-
//   conflict-free (kc*32 is 0 mod 32 banks unswizzled).
// ---------------------------------------------------------------------------
#define H_PITCH2 528                       // floats per staged h row
#define HSM_FLOATS (16 * H_PITCH2)         // 8448 floats = 33792 B
#define PSM_F4 (16 * 16 * 17)              // [jl][kc][b pad 17] = 69632 B
#define SMEM_RECUR (HSM_FLOATS * 4 + PSM_F4 * 16)   // 103424 B

__device__ __forceinline__ int hswz(int k4) {   // swizzled float4 slot
    return (k4 & ~7) | ((k4 ^ (k4 >> 3)) & 7);
}

__global__ void __launch_bounds__(256, 1) lstm_recur(const float* __restrict__ W_hh)
{
    extern __shared__ float smem[];
    float*  hsm = smem;                                 // [16][H_PITCH2]
    float4* psm = (float4*)(smem + HSM_FLOATS);         // [(jl*16+kc)*17 + b]

    const int tid = threadIdx.x;
    const int bl  = tid & 15;          // reduce-phase batch lane
    const int jl  = tid >> 4;          // unit lane (both phases)
    const int kc  = tid & 15;          // compute-phase k-chunk
    const int kcm = kc & 7;
    const int bg  = blockIdx.x & 3;
    const int jg  = blockIdx.x >> 2;
    const int b   = bg * 16 + bl;
    const int j   = jg * 16 + jl;
    const int j0  = jg * 16;

    // W registers: 4 gates x 32 k-floats for row (g*HH + j0+jl), cols kc*32..
    ulonglong2 wreg[4][8];
#pragma unroll
    for (int g = 0; g < 4; g++) {
        const float* wrow = W_hh + ((size_t)(g * HH + j0 + jl)) * HH + kc * 32;
#pragma unroll
        for (int q = 0; q < 8; q++)
            wreg[g][q] = *(const ulonglong2*)(wrow + q * 4);
    }

    // init read-buffer h to 0 and reset our flag slot (fresh every replay)
    __stcg(&g_h[0][b * HH + j], 0.0f);
    if (tid == 0) stcg_u32v(&g_flags[bg][jg][0], 0u);
    float c = 0.0f;

    // One-shot full-grid barrier: orders h-zero + flag resets across ALL CTAs.
    __threadfence();
    __syncthreads();
    if (tid == 0) {
        unsigned int my = *((volatile unsigned int*)&g_bar_gen);
        unsigned int arrived = atomicAdd(&g_bar_count, 1u);
        if (arrived == (unsigned)gridDim.x - 1) {
            atomicExch(&g_bar_count, 0u);
            __threadfence();
            atomicAdd(&g_bar_gen, 1u);
        } else {
            while (*((volatile unsigned int*)&g_bar_gen) == my) { __nanosleep(32); }
        }
        __threadfence();
    }
    __syncthreads();

    // Initial stage of h[0] (zeros; grid barrier ordered the writes).
    {
        const float* hsrc = &g_h[0][(bg * 16) * HH];
#pragma unroll
        for (int i = 0; i < 8; i++) {
            int idx  = i * 256 + tid;
            int brow = idx >> 7;
            int k4   = idx & 127;
            float4 v = __ldcg((const float4*)(hsrc + (size_t)brow * HH) + k4);
            *(float4*)(hsm + brow * H_PITCH2 + hswz(k4) * 4) = v;
        }
    }
    // Preload gate inputs for t=0 (reduce identity bl,jl).
    const float* xgp = &g_gates[(size_t)b * (4 * HH) + j];
    float xi  = __ldcg(xgp);
    float xf  = __ldcg(xgp + HH);
    float xgg = __ldcg(xgp + 2 * HH);
    float xo  = __ldcg(xgp + 3 * HH);
    __syncthreads();

    for (int t = 0; t < TT; t++) {
        // ---- compute phase: thread (jl, kc), all 16 batches ----
        float4* pout = &psm[(jl * 16 + kc) * 17];
#pragma unroll 2
        for (int bb = 0; bb < 16; bb++) {
            const float* hb = hsm + bb * H_PITCH2 + kc * 32;
            unsigned long long ai = 0ull, af = 0ull, ag = 0ull, ao = 0ull;
#pragma unroll
            for (int q = 0; q < 8; q++) {
                ulonglong2 h2 = *(const ulonglong2*)(hb + ((q ^ kcm) << 2));
                ffma2(ai, h2.x, wreg[0][q].x); ffma2(ai, h2.y, wreg[0][q].y);
                ffma2(af, h2.x, wreg[1][q].x); ffma2(af, h2.y, wreg[1][q].y);
                ffma2(ag, h2.x, wreg[2][q].x); ffma2(ag, h2.y, wreg[2][q].y);
                ffma2(ao, h2.x, wreg[3][q].x); ffma2(ao, h2.y, wreg[3][q].y);
            }
            float4 p;
            p.x = pairsum(ai); p.y = pairsum(af);
            p.z = pairsum(ag); p.w = pairsum(ao);
            pout[bb] = p;
        }
        __syncthreads();   // partials visible

        // ---- reduce phase: thread (bl, jl) ----
        float si = 0.f, sf = 0.f, sg = 0.f, so = 0.f;
#pragma unroll
        for (int kk = 0; kk < 16; kk++) {
            float4 p = psm[(jl * 16 + kk) * 17 + bl];
            si += p.x; sf += p.y; sg += p.z; so += p.w;
        }

        float gi = sigmoidf_(xi  + si);
        float gf = sigmoidf_(xf  + sf);
        float gg = tanhf    (xgg + sg);
        float go = sigmoidf_(xo  + so);
        c = gf * c + gi * gg;
        float hv = go * tanhf(c);
        __stcg(&g_h[(t + 1) & 1][b * HH + j], hv);

        if (t == TT - 1) {
            g_hs[((size_t)t * BB + b) * HH + j] = hv;
            break;
        }

        // ---- signal: fence own stores, CTA-sync, set flag (R8 protocol) ----
        __threadfence();
        __syncthreads();                 // also protects psm reuse next step
        if (tid == 0) stcg_u32v(&g_flags[bg][jg][0], (unsigned int)(t + 1));

        // History store + next-step gate prefetch ride the poll window.
        g_hs[((size_t)t * BB + b) * HH + j] = hv;
        {
            const float* xg = &g_gates[((size_t)(t + 1) * BB + b) * (4 * HH) + j];
            xi  = __ldcg(xg);
            xf  = __ldcg(xg + HH);
            xgg = __ldcg(xg + 2 * HH);
            xo  = __ldcg(xg + 3 * HH);
        }

        // ---- wait: warp 0 polls all 32 slots of this bg ----
        if (tid < 32) {
            unsigned int tgt = (unsigned int)(t + 1);
            while (true) {
                unsigned int f = ldcg_u32v(&g_flags[bg][tid][0]);
                if (__all_sync(0xffffffffu, f >= tgt)) break;
                __nanosleep(20);
            }
            __threadfence();             // acquire
        }
        __syncthreads();

        // ---- monolithic stage of h[t+1] (R8 pattern + swizzle) ----
        {
            const float* hsrc = &g_h[(t + 1) & 1][(bg * 16) * HH];
#pragma unroll
            for (int i = 0; i < 8; i++) {
                int idx  = i * 256 + tid;
                int brow = idx >> 7;
                int k4   = idx & 127;
                float4 v = __ldcg((const float4*)(hsrc + (size_t)brow * HH) + k4);
                *(float4*)(hsm + brow * H_PITCH2 + hswz(k4) * 4) = v;
            }
        }
        __syncthreads();   // staged h[t+1] visible
    }
}

// ---------------------------------------------------------------------------
// Phase 3: out[b][t][c] = hs[t][b][:] . W_fc[c][:] + b_fc[c]  (unchanged)
// ---------------------------------------------------------------------------
__global__ void __launch_bounds__(256) fc_gemm(
    const float* __restrict__ W_fc,
    const float* __restrict__ b_fc,
    float* __restrict__ out)
{
    __shared__ float As[8][128];
    __shared__ float Bs[8][128];

    const int m0 = blockIdx.x * 128;
    const int tid = threadIdx.x;
    const int tx = tid & 15;
    const int ty = tid >> 4;

    float acc[8][8];
#pragma unroll
    for (int i = 0; i < 8; i++)
#pragma unroll
        for (int j = 0; j < 8; j++) acc[i][j] = 0.0f;

    const int lr = tid >> 1;
    const int lk = (tid & 1) * 4;

    for (int k0 = 0; k0 < HH; k0 += 8) {
        {
            float4 v = *(const float4*)(g_hs + (size_t)(m0 + lr) * HH + k0 + lk);
            As[lk + 0][lr] = v.x; As[lk + 1][lr] = v.y;
            As[lk + 2][lr] = v.z; As[lk + 3][lr] = v.w;
        }
        {
            float4 v = *(const float4*)(W_fc + (size_t)lr * HH + k0 + lk);
            Bs[lk + 0][lr] = v.x; Bs[lk + 1][lr] = v.y;
            Bs[lk + 2][lr] = v.z; Bs[lk + 3][lr] = v.w;
        }
        __syncthreads();
#pragma unroll
        for (int k = 0; k < 8; k++) {
            float a[8], b[8];
            float4 a0 = *(const float4*)&As[k][ty * 4];
            float4 a1 = *(const float4*)&As[k][64 + ty * 4];
            float4 b0 = *(const float4*)&Bs[k][tx * 4];
            float4 b1 = *(const float4*)&Bs[k][64 + tx * 4];
            a[0]=a0.x; a[1]=a0.y; a[2]=a0.z; a[3]=a0.w;
            a[4]=a1.x; a[5]=a1.y; a[6]=a1.z; a[7]=a1.w;
            b[0]=b0.x; b[1]=b0.y; b[2]=b0.z; b[3]=b0.w;
            b[4]=b1.x; b[5]=b1.y; b[6]=b1.z; b[7]=b1.w;
#pragma unroll
            for (int i = 0; i < 8; i++)
#pragma unroll
                for (int j = 0; j < 8; j++)
                    acc[i][j] = fmaf(a[i], b[j], acc[i][j]);
        }
        __syncthreads();
    }

#pragma unroll
    for (int i = 0; i < 8; i++) {
        int m = m0 + (i >> 2) * 64 + ty * 4 + (i & 3);
        int bb = m & 63;
        int tt = m >> 6;
        size_t orow = ((size_t)bb * TT + tt) * CC;
#pragma unroll
        for (int j = 0; j < 8; j++) {
            int cc = (j >> 2) * 64 + tx * 4 + (j & 3);
            out[orow + cc] = acc[i][j] + b_fc[cc];
        }
    }
}

// ---------------------------------------------------------------------------
extern "C" void kernel_launch(void* const* d_in, const int* in_sizes, int n_in,
                              void* d_out, int out_size)
{
    const float* x    = (const float*)d_in[0];
    const float* W_ih = (const float*)d_in[1];
    const float* W_hh = (const float*)d_in[2];
    const float* b_ih = (const float*)d_in[3];
    const float* b_hh = (const float*)d_in[4];
    const float* W_fc = (const float*)d_in[5];
    const float* b_fc = (const float*)d_in[6];
    float* out = (float*)d_out;

    cudaFuncSetAttribute(lstm_recur,
                         cudaFuncAttributeMaxDynamicSharedMemorySize,
                         SMEM_RECUR);

    dim3 g1(4 * HH / 128, (BB * TT) / 128);   // (16, 256)
    gates_gemm<<<g1, 256>>>(x, W_ih, b_ih, b_hh);

    lstm_recur<<<128, 256, SMEM_RECUR>>>(W_hh);   // 128 CTAs, co-resident

    fc_gemm<<<(BB * TT) / 128, 256>>>(W_fc, b_fc, out);
}